// round 6
// baseline (speedup 1.0000x reference)
#include <cuda_runtime.h>
#include <cuda_bf16.h>
#include <math.h>
#include <stdint.h>

#define Bz  8
#define Tz  512
#define Hz  768
#define NHz 12
#define HDz 64
#define FFz 3072
#define Lz  12
#define Mz  (Bz*Tz)   // 4096

// ---------------- fp32 scratch ----------------
__device__ float g_q[Mz*Hz];
__device__ float g_k[Mz*Hz];
__device__ float g_v[Mz*Hz];
__device__ float g_proj[Mz*Hz];
__device__ float g_attn[Mz*Hz];
__device__ float g_x[Mz*Hz];

// ---------------- split (hi/lo bf16) activation scratch ----------------
__device__ __nv_bfloat16 g_x_h[Mz*Hz],    g_x_l[Mz*Hz];
__device__ __nv_bfloat16 g_attn_h[Mz*Hz], g_attn_l[Mz*Hz];
__device__ __nv_bfloat16 g_ctx_h[Mz*Hz],  g_ctx_l[Mz*Hz];
__device__ __nv_bfloat16 g_ff_h[Mz*FFz],  g_ff_l[Mz*FFz];

// ---------------- split weight storage ([L][K][N], hi/lo) ----------------
__device__ __nv_bfloat16 g_wq_h[Lz*Hz*Hz],  g_wq_l[Lz*Hz*Hz];
__device__ __nv_bfloat16 g_wk_h[Lz*Hz*Hz],  g_wk_l[Lz*Hz*Hz];
__device__ __nv_bfloat16 g_wv_h[Lz*Hz*Hz],  g_wv_l[Lz*Hz*Hz];
__device__ __nv_bfloat16 g_wao_h[Lz*Hz*Hz], g_wao_l[Lz*Hz*Hz];
__device__ __nv_bfloat16 g_wi_h[Lz*Hz*FFz], g_wi_l[Lz*Hz*FFz];
__device__ __nv_bfloat16 g_wo_h[Lz*Hz*FFz], g_wo_l[Lz*Hz*FFz];

// ---------------- helpers ----------------
__device__ __forceinline__ void split1(float x, __nv_bfloat16& h, __nv_bfloat16& l) {
    h = __float2bfloat16(x);
    l = __float2bfloat16(x - __bfloat162float(h));
}
__device__ __forceinline__ void split2(float x, float y, uint32_t& hi, uint32_t& lo) {
    __nv_bfloat16 xh, xl, yh, yl;
    split1(x, xh, xl); split1(y, yh, yl);
    hi = (uint32_t)__bfloat16_as_ushort(xh) | ((uint32_t)__bfloat16_as_ushort(yh) << 16);
    lo = (uint32_t)__bfloat16_as_ushort(xl) | ((uint32_t)__bfloat16_as_ushort(yl) << 16);
}

__global__ __launch_bounds__(256) void split_kernel(
    const float* __restrict__ in, __nv_bfloat16* __restrict__ h,
    __nv_bfloat16* __restrict__ l, int n4)
{
    int i = blockIdx.x * 256 + threadIdx.x;
    if (i >= n4) return;
    float4 v = ((const float4*)in)[i];
    uint32_t h01, l01, h23, l23;
    split2(v.x, v.y, h01, l01);
    split2(v.z, v.w, h23, l23);
    ((uint2*)h)[i] = make_uint2(h01, h23);
    ((uint2*)l)[i] = make_uint2(l01, l23);
}

// ================= bf16x3 mma.sync GEMM (BK=32, 3 stages, 2 CTAs/SM) =================
#define BM 128
#define BN 128
#define BK2 32

#define ASZ (BM*BK2)              // 4096 elems / plane
#define BSZ (BK2*BN)              // 4096 elems / plane
#define STG_ELEMS (2*ASZ+2*BSZ)   // 16384 elems = 32KB
#define ASOFF(s,pl,m,k)  ((s)*STG_ELEMS + (pl)*ASZ + (m)*BK2 + (k))
#define BSOFF(s,pl,kk,n) ((s)*STG_ELEMS + 2*ASZ + (pl)*BSZ + (kk)*BN + (n))
#define GEMM_SMEM (3*STG_ELEMS*2) // 98304 bytes

struct GemmArgs {
    const __nv_bfloat16 *Ah, *Al;
    const __nv_bfloat16 *Bh[3], *Bl[3];
    const float* bias[3];
    float* C[3];
    __nv_bfloat16 *Ch, *Cl;
};

__device__ __forceinline__ void cpa16(void* dst, const void* src) {
    uint32_t d = (uint32_t)__cvta_generic_to_shared(dst);
    asm volatile("cp.async.cg.shared.global [%0], [%1], 16;" :: "r"(d), "l"(src));
}
__device__ __forceinline__ void ldsm4(uint32_t* r, const void* p) {
    uint32_t a = (uint32_t)__cvta_generic_to_shared(p);
    asm volatile("ldmatrix.sync.aligned.m8n8.x4.shared.b16 {%0,%1,%2,%3}, [%4];"
                 : "=r"(r[0]), "=r"(r[1]), "=r"(r[2]), "=r"(r[3]) : "r"(a));
}
__device__ __forceinline__ void ldsm4t(uint32_t* r, const void* p) {
    uint32_t a = (uint32_t)__cvta_generic_to_shared(p);
    asm volatile("ldmatrix.sync.aligned.m8n8.x4.trans.shared.b16 {%0,%1,%2,%3}, [%4];"
                 : "=r"(r[0]), "=r"(r[1]), "=r"(r[2]), "=r"(r[3]) : "r"(a));
}
__device__ __forceinline__ void mma16816(float* c, const uint32_t* a, const uint32_t* b) {
    asm volatile(
        "mma.sync.aligned.m16n8k16.row.col.f32.bf16.bf16.f32 "
        "{%0,%1,%2,%3}, {%4,%5,%6,%7}, {%8,%9}, {%0,%1,%2,%3};"
        : "+f"(c[0]), "+f"(c[1]), "+f"(c[2]), "+f"(c[3])
        : "r"(a[0]), "r"(a[1]), "r"(a[2]), "r"(a[3]), "r"(b[0]), "r"(b[1]));
}

// MODE 0: fp32 out (+bias). MODE 1: bias + exact GELU, split bf16 out.
template<int MODE>
__global__ __launch_bounds__(256, 2) void gemm_bf16x3(GemmArgs P, int K, int N)
{
    extern __shared__ __align__(16) __nv_bfloat16 sm[];

    const int z = blockIdx.z;
    const __nv_bfloat16* __restrict__ Ah = P.Ah;
    const __nv_bfloat16* __restrict__ Al = P.Al;
    const __nv_bfloat16* __restrict__ Bh = P.Bh[z];
    const __nv_bfloat16* __restrict__ Bl = P.Bl[z];
    const float* __restrict__ bias = P.bias[z];

    const int n0 = blockIdx.x * BN;
    const int m0 = blockIdx.y * BM;
    const int tid  = threadIdx.x;
    const int lane = tid & 31;
    const int warp = tid >> 5;
    const int warpM = warp >> 2;   // 0..1
    const int warpN = warp & 3;    // 0..3

    const int nT = K / BK2;

    auto issue = [&](int t, int s) {
        const int k0 = t * BK2;
#pragma unroll
        for (int p = 0; p < 2; p++) {
            const int idx = tid + p * 256;
            const int ar = idx >> 2, ac = (idx & 3) * 8;       // 128 rows x 32 cols
            cpa16(sm + ASOFF(s, 0, ar, ac), Ah + (size_t)(m0 + ar) * K + k0 + ac);
            cpa16(sm + ASOFF(s, 1, ar, ac), Al + (size_t)(m0 + ar) * K + k0 + ac);
            const int br = idx >> 4, bc = (idx & 15) * 8;      // 32 rows x 128 cols
            cpa16(sm + BSOFF(s, 0, br, bc), Bh + (size_t)(k0 + br) * N + n0 + bc);
            cpa16(sm + BSOFF(s, 1, br, bc), Bl + (size_t)(k0 + br) * N + n0 + bc);
        }
        asm volatile("cp.async.commit_group;" ::: "memory");
    };

    issue(0, 0);
    issue(1, 1);

    float acc[4][4][4] = {};
    int s = 0;

    for (int t = 0; t < nT; t++) {
        if (t + 1 < nT) asm volatile("cp.async.wait_group 1;" ::: "memory");
        else            asm volatile("cp.async.wait_group 0;" ::: "memory");
        __syncthreads();

#pragma unroll
        for (int sub = 0; sub < 2; sub++) {
            uint32_t ah[4][4], al[4][4], bh[4][2], bl[4][2];
            const int arow = warpM * 64 + (lane & 15);
            const int acol = sub * 16 + (lane >> 4) * 8;
#pragma unroll
            for (int mi = 0; mi < 4; mi++) {
                ldsm4(ah[mi], sm + ASOFF(s, 0, arow + mi * 16, acol));
                ldsm4(al[mi], sm + ASOFF(s, 1, arow + mi * 16, acol));
            }
            const int brow = sub * 16 + (lane & 15);
#pragma unroll
            for (int pr = 0; pr < 2; pr++) {
                const int bcol = warpN * 32 + pr * 16 + (lane >> 4) * 8;
                uint32_t tmp[4];
                ldsm4t(tmp, sm + BSOFF(s, 0, brow, bcol));
                bh[pr * 2][0] = tmp[0]; bh[pr * 2][1] = tmp[1];
                bh[pr * 2 + 1][0] = tmp[2]; bh[pr * 2 + 1][1] = tmp[3];
                ldsm4t(tmp, sm + BSOFF(s, 1, brow, bcol));
                bl[pr * 2][0] = tmp[0]; bl[pr * 2][1] = tmp[1];
                bl[pr * 2 + 1][0] = tmp[2]; bl[pr * 2 + 1][1] = tmp[3];
            }
#pragma unroll
            for (int mi = 0; mi < 4; mi++)
#pragma unroll
                for (int ni = 0; ni < 4; ni++) {
                    mma16816(acc[mi][ni], ah[mi], bh[ni]);
                    mma16816(acc[mi][ni], ah[mi], bl[ni]);
                    mma16816(acc[mi][ni], al[mi], bh[ni]);
                }
        }
        // stage (t+2)%3 was last read at iter t-1; the barrier above makes reuse safe
        if (t + 2 < nT) {
            int s2 = s + 2; if (s2 >= 3) s2 -= 3;
            issue(t + 2, s2);
        }
        if (++s == 3) s = 0;
    }

    // epilogue
    const int g  = lane >> 2;
    const int tg = lane & 3;
#pragma unroll
    for (int mi = 0; mi < 4; mi++) {
#pragma unroll
        for (int ni = 0; ni < 4; ni++) {
            const int row = m0 + warpM * 64 + mi * 16 + g;
            const int col = n0 + warpN * 32 + ni * 8 + tg * 2;
            const float b0 = bias[col], b1 = bias[col + 1];
            float v0 = acc[mi][ni][0] + b0;
            float v1 = acc[mi][ni][1] + b1;
            float v2 = acc[mi][ni][2] + b0;
            float v3 = acc[mi][ni][3] + b1;
            if (MODE == 1) {
                v0 = 0.5f * v0 * (1.0f + erff(v0 * 0.70710678118654752f));
                v1 = 0.5f * v1 * (1.0f + erff(v1 * 0.70710678118654752f));
                v2 = 0.5f * v2 * (1.0f + erff(v2 * 0.70710678118654752f));
                v3 = 0.5f * v3 * (1.0f + erff(v3 * 0.70710678118654752f));
                uint32_t hw, lw;
                split2(v0, v1, hw, lw);
                *(uint32_t*)(P.Ch + (size_t)row * N + col) = hw;
                *(uint32_t*)(P.Cl + (size_t)row * N + col) = lw;
                split2(v2, v3, hw, lw);
                *(uint32_t*)(P.Ch + (size_t)(row + 8) * N + col) = hw;
                *(uint32_t*)(P.Cl + (size_t)(row + 8) * N + col) = lw;
            } else {
                float* C = P.C[z];
                *(float2*)(C + (size_t)row * N + col)       = make_float2(v0, v1);
                *(float2*)(C + (size_t)(row + 8) * N + col) = make_float2(v2, v3);
            }
        }
    }
}

// ---------------- fused attention (flash-style, fp32; split bf16 out) ----------------
#define SMPAD 65
__global__ __launch_bounds__(256) void attention_kernel(
    const float* __restrict__ q, const float* __restrict__ k,
    const float* __restrict__ v, const float* __restrict__ mask,
    __nv_bfloat16* __restrict__ ctx_h, __nv_bfloat16* __restrict__ ctx_l)
{
    extern __shared__ float smf[];
    float* Qs = smf;
    float* Ks = Qs + 64 * SMPAD;
    float* Vs = Ks + 64 * SMPAD;
    float* Ps = Vs + 64 * SMPAD;
    float* rm = Ps + 64 * SMPAD;
    float* rl = rm + 64;
    float* rs = rl + 64;
    float* am = rs + 64;

    const int tx = threadIdx.x, ty = threadIdx.y;
    const int tid = ty * 16 + tx;
    const int bh = blockIdx.y;
    const int b = bh / NHz, h = bh % NHz;
    const int i0 = blockIdx.x * 64;
    const float scale = 0.125f;

#pragma unroll
    for (int it = 0; it < 4; it++) {
        int idx = tid + it * 256;
        int row = idx >> 4;
        int d4 = (idx & 15) * 4;
        float4 t = *(const float4*)(q + (size_t)(b * Tz + i0 + row) * Hz + h * HDz + d4);
        Qs[row * SMPAD + d4 + 0] = t.x;
        Qs[row * SMPAD + d4 + 1] = t.y;
        Qs[row * SMPAD + d4 + 2] = t.z;
        Qs[row * SMPAD + d4 + 3] = t.w;
    }
    if (tid < 64) { rm[tid] = -1e30f; rl[tid] = 0.0f; }

    float acc[4][4] = {};

    for (int jc = 0; jc < Tz / 64; jc++) {
        const int j0 = jc * 64;
#pragma unroll
        for (int it = 0; it < 4; it++) {
            int idx = tid + it * 256;
            int row = idx >> 4;
            int d4 = (idx & 15) * 4;
            float4 t = *(const float4*)(k + (size_t)(b * Tz + j0 + row) * Hz + h * HDz + d4);
            Ks[row * SMPAD + d4 + 0] = t.x;
            Ks[row * SMPAD + d4 + 1] = t.y;
            Ks[row * SMPAD + d4 + 2] = t.z;
            Ks[row * SMPAD + d4 + 3] = t.w;
        }
        if (tid < 64) am[tid] = (1.0f - mask[b * Tz + j0 + tid]) * -10000.0f;
        __syncthreads();

        float s[4][4] = {};
#pragma unroll 4
        for (int d = 0; d < 64; d++) {
            float qv[4], kv[4];
#pragma unroll
            for (int i = 0; i < 4; i++) qv[i] = Qs[(ty + 16 * i) * SMPAD + d];
#pragma unroll
            for (int j = 0; j < 4; j++) kv[j] = Ks[(tx + 16 * j) * SMPAD + d];
#pragma unroll
            for (int i = 0; i < 4; i++)
#pragma unroll
                for (int j = 0; j < 4; j++)
                    s[i][j] = fmaf(qv[i], kv[j], s[i][j]);
        }
#pragma unroll
        for (int i = 0; i < 4; i++)
#pragma unroll
            for (int j = 0; j < 4; j++)
                Ps[(ty + 16 * i) * SMPAD + tx + 16 * j] = s[i][j] * scale + am[tx + 16 * j];
        __syncthreads();

        // load V chunk (same threads also do softmax below; V load first for MLP)
#pragma unroll
        for (int it = 0; it < 4; it++) {
            int idx = tid + it * 256;
            int row = idx >> 4;
            int d4 = (idx & 15) * 4;
            float4 t = *(const float4*)(v + (size_t)(b * Tz + j0 + row) * Hz + h * HDz + d4);
            Vs[row * SMPAD + d4 + 0] = t.x;
            Vs[row * SMPAD + d4 + 1] = t.y;
            Vs[row * SMPAD + d4 + 2] = t.z;
            Vs[row * SMPAD + d4 + 3] = t.w;
        }

        // parallel online softmax: 4 threads per row, 16 cols each
        {
            const int srow = tid >> 2;
            const int ssub = tid & 3;
            float* prow = Ps + srow * SMPAD + ssub * 16;
            const float mo = rm[srow];
            float pv[16];
            float cm = -1e30f;
#pragma unroll
            for (int jj = 0; jj < 16; jj++) {
                pv[jj] = prow[jj];
                cm = fmaxf(cm, pv[jj]);
            }
            cm = fmaxf(cm, __shfl_xor_sync(0xffffffffu, cm, 1));
            cm = fmaxf(cm, __shfl_xor_sync(0xffffffffu, cm, 2));
            const float nm = fmaxf(mo, cm);
            float sum = 0.0f;
#pragma unroll
            for (int jj = 0; jj < 16; jj++) {
                float p = __expf(pv[jj] - nm);
                prow[jj] = p;
                sum += p;
            }
            sum += __shfl_xor_sync(0xffffffffu, sum, 1);
            sum += __shfl_xor_sync(0xffffffffu, sum, 2);
            if (ssub == 0) {
                const float sc = __expf(mo - nm);
                rl[srow] = rl[srow] * sc + sum;
                rm[srow] = nm;
                rs[srow] = sc;
            }
        }
        __syncthreads();

#pragma unroll
        for (int i = 0; i < 4; i++) {
            const float sc = rs[ty + 16 * i];
#pragma unroll
            for (int j = 0; j < 4; j++) acc[i][j] *= sc;
        }
#pragma unroll 4
        for (int jj = 0; jj < 64; jj++) {
            float pv[4], vv[4];
#pragma unroll
            for (int i = 0; i < 4; i++) pv[i] = Ps[(ty + 16 * i) * SMPAD + jj];
#pragma unroll
            for (int j = 0; j < 4; j++) vv[j] = Vs[jj * SMPAD + tx + 16 * j];
#pragma unroll
            for (int i = 0; i < 4; i++)
#pragma unroll
                for (int j = 0; j < 4; j++)
                    acc[i][j] = fmaf(pv[i], vv[j], acc[i][j]);
        }
        __syncthreads();
    }

#pragma unroll
    for (int i = 0; i < 4; i++) {
        const float inv = 1.0f / rl[ty + 16 * i];
#pragma unroll
        for (int j = 0; j < 4; j++) {
            size_t off = (size_t)(b * Tz + i0 + ty + 16 * i) * Hz + h * HDz + tx + 16 * j;
            float val = acc[i][j] * inv;
            __nv_bfloat16 hv, lv;
            split1(val, hv, lv);
            ctx_h[off] = hv;
            ctx_l[off] = lv;
        }
    }
}

// ---------------- residual + LayerNorm (fp32 + split out) ----------------
__device__ __forceinline__ float block_reduce_sum(float val, float* red) {
    const int lane = threadIdx.x & 31, w = threadIdx.x >> 5;
#pragma unroll
    for (int o = 16; o > 0; o >>= 1) val += __shfl_down_sync(0xffffffffu, val, o);
    if (lane == 0) red[w] = val;
    __syncthreads();
    if (w == 0) {
        float t = (lane < 8) ? red[lane] : 0.0f;
#pragma unroll
        for (int o = 4; o > 0; o >>= 1) t += __shfl_down_sync(0xffffffffu, t, o);
        if (lane == 0) red[0] = t;
    }
    __syncthreads();
    float r = red[0];
    __syncthreads();
    return r;
}

__global__ __launch_bounds__(256) void ln_kernel(
    const float* __restrict__ a, const float* __restrict__ res,
    const float* __restrict__ g, const float* __restrict__ bb,
    float* __restrict__ out,
    __nv_bfloat16* __restrict__ oh, __nv_bfloat16* __restrict__ ol)
{
    __shared__ float buf[Hz];
    __shared__ float red[32];
    const int row = blockIdx.x;
    const float* ap = a + (size_t)row * Hz;
    const float* rp = res + (size_t)row * Hz;

    float ls = 0.0f;
    for (int i = threadIdx.x; i < Hz; i += 256) {
        float vv = ap[i] + rp[i];
        buf[i] = vv;
        ls += vv;
    }
    const float mean = block_reduce_sum(ls, red) * (1.0f / Hz);

    float lq = 0.0f;
    for (int i = threadIdx.x; i < Hz; i += 256) {
        float d = buf[i] - mean;
        lq += d * d;
    }
    const float var = block_reduce_sum(lq, red) * (1.0f / Hz);
    const float rstd = rsqrtf(var + 1e-12f);

    for (int i = threadIdx.x; i < Hz; i += 256) {
        float y = (buf[i] - mean) * rstd * g[i] + bb[i];
        out[(size_t)row * Hz + i] = y;
        __nv_bfloat16 hv, lv;
        split1(y, hv, lv);
        oh[(size_t)row * Hz + i] = hv;
        ol[(size_t)row * Hz + i] = lv;
    }
}

// ---------------- launch ----------------
extern "C" void kernel_launch(void* const* d_in, const int* in_sizes, int n_in,
                              void* d_out, int out_size)
{
    const float* hidden = (const float*)d_in[0];
    const float* mask   = (const float*)d_in[1];
    const float* Wq  = (const float*)d_in[2];   const float* bq  = (const float*)d_in[3];
    const float* Wk  = (const float*)d_in[4];   const float* bk  = (const float*)d_in[5];
    const float* Wv  = (const float*)d_in[6];   const float* bv  = (const float*)d_in[7];
    const float* Wao = (const float*)d_in[8];   const float* bao = (const float*)d_in[9];
    const float* g1  = (const float*)d_in[10];  const float* b1  = (const float*)d_in[11];
    const float* Wi  = (const float*)d_in[12];  const float* bi  = (const float*)d_in[13];
    const float* Wo  = (const float*)d_in[14];  const float* bo  = (const float*)d_in[15];
    const float* g2  = (const float*)d_in[16];  const float* b2  = (const float*)d_in[17];
    float* out = (float*)d_out;

    float *q, *k, *v, *proj, *attn, *xb;
    cudaGetSymbolAddress((void**)&q,    g_q);
    cudaGetSymbolAddress((void**)&k,    g_k);
    cudaGetSymbolAddress((void**)&v,    g_v);
    cudaGetSymbolAddress((void**)&proj, g_proj);
    cudaGetSymbolAddress((void**)&attn, g_attn);
    cudaGetSymbolAddress((void**)&xb,   g_x);

    __nv_bfloat16 *xh, *xl, *ath, *atl, *cth, *ctl, *ffh, *ffl;
    cudaGetSymbolAddress((void**)&xh,  g_x_h);    cudaGetSymbolAddress((void**)&xl,  g_x_l);
    cudaGetSymbolAddress((void**)&ath, g_attn_h); cudaGetSymbolAddress((void**)&atl, g_attn_l);
    cudaGetSymbolAddress((void**)&cth, g_ctx_h);  cudaGetSymbolAddress((void**)&ctl, g_ctx_l);
    cudaGetSymbolAddress((void**)&ffh, g_ff_h);   cudaGetSymbolAddress((void**)&ffl, g_ff_l);

    __nv_bfloat16 *wqh, *wql, *wkh, *wkl, *wvh, *wvl, *waoh, *waol, *wih, *wil, *woh, *wol;
    cudaGetSymbolAddress((void**)&wqh,  g_wq_h);  cudaGetSymbolAddress((void**)&wql,  g_wq_l);
    cudaGetSymbolAddress((void**)&wkh,  g_wk_h);  cudaGetSymbolAddress((void**)&wkl,  g_wk_l);
    cudaGetSymbolAddress((void**)&wvh,  g_wv_h);  cudaGetSymbolAddress((void**)&wvl,  g_wv_l);
    cudaGetSymbolAddress((void**)&waoh, g_wao_h); cudaGetSymbolAddress((void**)&waol, g_wao_l);
    cudaGetSymbolAddress((void**)&wih,  g_wi_h);  cudaGetSymbolAddress((void**)&wil,  g_wi_l);
    cudaGetSymbolAddress((void**)&woh,  g_wo_h);  cudaGetSymbolAddress((void**)&wol,  g_wo_l);

    // pre-split weights + input
    const int nHH = Lz * Hz * Hz, nHF = Lz * Hz * FFz, nX = Mz * Hz;
    split_kernel<<<nHH / 1024, 256>>>(Wq,  wqh,  wql,  nHH / 4);
    split_kernel<<<nHH / 1024, 256>>>(Wk,  wkh,  wkl,  nHH / 4);
    split_kernel<<<nHH / 1024, 256>>>(Wv,  wvh,  wvl,  nHH / 4);
    split_kernel<<<nHH / 1024, 256>>>(Wao, waoh, waol, nHH / 4);
    split_kernel<<<nHF / 1024, 256>>>(Wi,  wih,  wil,  nHF / 4);
    split_kernel<<<nHF / 1024, 256>>>(Wo,  woh,  wol,  nHF / 4);
    split_kernel<<<nX  / 1024, 256>>>(hidden, xh, xl, nX / 4);

    const size_t att_smem  = (size_t)(4 * 64 * SMPAD + 4 * 64) * sizeof(float);
    cudaFuncSetAttribute(attention_kernel,
                         cudaFuncAttributeMaxDynamicSharedMemorySize, (int)att_smem);
    cudaFuncSetAttribute(gemm_bf16x3<0>,
                         cudaFuncAttributeMaxDynamicSharedMemorySize, GEMM_SMEM);
    cudaFuncSetAttribute(gemm_bf16x3<1>,
                         cudaFuncAttributeMaxDynamicSharedMemorySize, GEMM_SMEM);

    dim3 gAtt(Tz / 64, Bz * NHz);
    dim3 blkA(16, 16);

    for (int l = 0; l < Lz; l++) {
        const float* xres = (l == 0) ? hidden : xb;
        const size_t oHH = (size_t)l * Hz * Hz;
        const size_t oHF = (size_t)l * Hz * FFz;
        const size_t oH  = (size_t)l * Hz;
        const size_t oF  = (size_t)l * FFz;

        {   // fused QKV
            GemmArgs P = {};
            P.Ah = xh; P.Al = xl;
            P.Bh[0] = wqh + oHH; P.Bl[0] = wql + oHH;
            P.Bh[1] = wkh + oHH; P.Bl[1] = wkl + oHH;
            P.Bh[2] = wvh + oHH; P.Bl[2] = wvl + oHH;
            P.bias[0] = bq + oH; P.bias[1] = bk + oH; P.bias[2] = bv + oH;
            P.C[0] = q; P.C[1] = k; P.C[2] = v;
            gemm_bf16x3<0><<<dim3(Hz / BN, Mz / BM, 3), 256, GEMM_SMEM>>>(P, Hz, Hz);
        }

        attention_kernel<<<gAtt, blkA, att_smem>>>(q, k, v, mask, cth, ctl);

        {   // attention output projection
            GemmArgs P = {};
            P.Ah = cth; P.Al = ctl;
            P.Bh[0] = waoh + oHH; P.Bl[0] = waol + oHH;
            P.bias[0] = bao + oH;
            P.C[0] = proj;
            gemm_bf16x3<0><<<dim3(Hz / BN, Mz / BM, 1), 256, GEMM_SMEM>>>(P, Hz, Hz);
        }
        ln_kernel<<<Mz, 256>>>(proj, xres, g1 + oH, b1 + oH, attn, ath, atl);

        {   // FF1 + GELU (split bf16 out)
            GemmArgs P = {};
            P.Ah = ath; P.Al = atl;
            P.Bh[0] = wih + oHF; P.Bl[0] = wil + oHF;
            P.bias[0] = bi + oF;
            P.Ch = ffh; P.Cl = ffl;
            gemm_bf16x3<1><<<dim3(FFz / BN, Mz / BM, 1), 256, GEMM_SMEM>>>(P, Hz, FFz);
        }
        {   // FF2
            GemmArgs P = {};
            P.Ah = ffh; P.Al = ffl;
            P.Bh[0] = woh + oHF; P.Bl[0] = wol + oHF;
            P.bias[0] = bo + oH;
            P.C[0] = proj;
            gemm_bf16x3<0><<<dim3(Hz / BN, Mz / BM, 1), 256, GEMM_SMEM>>>(P, FFz, Hz);
        }
        ln_kernel<<<Mz, 256>>>(proj, attn, g2 + oH, b2 + oH,
                               (l == Lz - 1) ? out : xb, xh, xl);
    }
}

// round 7
// speedup vs baseline: 2.7789x; 2.7789x over previous
#include <cuda_runtime.h>
#include <cuda_bf16.h>
#include <math.h>
#include <stdint.h>

#define Bz  8
#define Tz  512
#define Hz  768
#define NHz 12
#define HDz 64
#define FFz 3072
#define Lz  12
#define Mz  (Bz*Tz)   // 4096

// ---------------- fp32 scratch ----------------
__device__ float g_q[Mz*Hz];
__device__ float g_k[Mz*Hz];
__device__ float g_v[Mz*Hz];
__device__ float g_proj[Mz*Hz];
__device__ float g_attn[Mz*Hz];
__device__ float g_x[Mz*Hz];

// ---------------- split (hi/lo bf16) activation scratch ----------------
__device__ __nv_bfloat16 g_x_h[Mz*Hz],    g_x_l[Mz*Hz];
__device__ __nv_bfloat16 g_attn_h[Mz*Hz], g_attn_l[Mz*Hz];
__device__ __nv_bfloat16 g_ctx_h[Mz*Hz],  g_ctx_l[Mz*Hz];
__device__ __nv_bfloat16 g_ff_h[Mz*FFz],  g_ff_l[Mz*FFz];

// ---------------- split weight storage ([L][K][N], hi/lo) ----------------
__device__ __nv_bfloat16 g_wq_h[Lz*Hz*Hz],  g_wq_l[Lz*Hz*Hz];
__device__ __nv_bfloat16 g_wk_h[Lz*Hz*Hz],  g_wk_l[Lz*Hz*Hz];
__device__ __nv_bfloat16 g_wv_h[Lz*Hz*Hz],  g_wv_l[Lz*Hz*Hz];
__device__ __nv_bfloat16 g_wao_h[Lz*Hz*Hz], g_wao_l[Lz*Hz*Hz];
__device__ __nv_bfloat16 g_wi_h[Lz*Hz*FFz], g_wi_l[Lz*Hz*FFz];
__device__ __nv_bfloat16 g_wo_h[Lz*Hz*FFz], g_wo_l[Lz*Hz*FFz];

// ---------------- helpers ----------------
__device__ __forceinline__ void split1(float x, __nv_bfloat16& h, __nv_bfloat16& l) {
    h = __float2bfloat16(x);
    l = __float2bfloat16(x - __bfloat162float(h));
}
__device__ __forceinline__ void split2(float x, float y, uint32_t& hi, uint32_t& lo) {
    __nv_bfloat16 xh, xl, yh, yl;
    split1(x, xh, xl); split1(y, yh, yl);
    hi = (uint32_t)__bfloat16_as_ushort(xh) | ((uint32_t)__bfloat16_as_ushort(yh) << 16);
    lo = (uint32_t)__bfloat16_as_ushort(xl) | ((uint32_t)__bfloat16_as_ushort(yl) << 16);
}

__global__ __launch_bounds__(256) void split_kernel(
    const float* __restrict__ in, __nv_bfloat16* __restrict__ h,
    __nv_bfloat16* __restrict__ l, int n4)
{
    int i = blockIdx.x * 256 + threadIdx.x;
    if (i >= n4) return;
    float4 v = ((const float4*)in)[i];
    uint32_t h01, l01, h23, l23;
    split2(v.x, v.y, h01, l01);
    split2(v.z, v.w, h23, l23);
    ((uint2*)h)[i] = make_uint2(h01, h23);
    ((uint2*)l)[i] = make_uint2(l01, l23);
}

// ===== bf16x3 mma.sync GEMM: BK=32, 3 stages, XOR-swizzled smem, 2 CTAs/SM =====
#define BM 128
#define BN 128
#define BK2 32

#define PLANE 4096                 // elems per plane (A: 128x32, B: 32x128)
#define STG_ELEMS (4*PLANE)        // 16384 elems = 32KB per stage
#define GEMM_SMEM (3*STG_ELEMS*2)  // 98304 bytes

// A plane: row m (0..127), 16B-chunk c (0..3). phys chunk = c ^ ((m>>1)&3)
#define ASOFFZ(s,pl,m,c)  ((s)*STG_ELEMS + (pl)*PLANE + (m)*32  + ((((c) ^ (((m)>>1)&3)))<<3))
// B plane: row kk (0..31), 16B-chunk c (0..15). phys chunk = c ^ (kk&7)
#define BSOFFZ(s,pl,kk,c) ((s)*STG_ELEMS + 2*PLANE + (pl)*PLANE + (kk)*128 + ((((c) ^ ((kk)&7)))<<3))

struct GemmArgs {
    const __nv_bfloat16 *Ah, *Al;
    const __nv_bfloat16 *Bh[3], *Bl[3];
    const float* bias[3];
    float* C[3];
    __nv_bfloat16 *Ch, *Cl;
};

__device__ __forceinline__ void cpa16(void* dst, const void* src) {
    uint32_t d = (uint32_t)__cvta_generic_to_shared(dst);
    asm volatile("cp.async.cg.shared.global [%0], [%1], 16;" :: "r"(d), "l"(src));
}
__device__ __forceinline__ void ldsm4(uint32_t* r, const void* p) {
    uint32_t a = (uint32_t)__cvta_generic_to_shared(p);
    asm volatile("ldmatrix.sync.aligned.m8n8.x4.shared.b16 {%0,%1,%2,%3}, [%4];"
                 : "=r"(r[0]), "=r"(r[1]), "=r"(r[2]), "=r"(r[3]) : "r"(a));
}
__device__ __forceinline__ void ldsm4t(uint32_t* r, const void* p) {
    uint32_t a = (uint32_t)__cvta_generic_to_shared(p);
    asm volatile("ldmatrix.sync.aligned.m8n8.x4.trans.shared.b16 {%0,%1,%2,%3}, [%4];"
                 : "=r"(r[0]), "=r"(r[1]), "=r"(r[2]), "=r"(r[3]) : "r"(a));
}
__device__ __forceinline__ void mma16816(float* c, const uint32_t* a, const uint32_t* b) {
    asm volatile(
        "mma.sync.aligned.m16n8k16.row.col.f32.bf16.bf16.f32 "
        "{%0,%1,%2,%3}, {%4,%5,%6,%7}, {%8,%9}, {%0,%1,%2,%3};"
        : "+f"(c[0]), "+f"(c[1]), "+f"(c[2]), "+f"(c[3])
        : "r"(a[0]), "r"(a[1]), "r"(a[2]), "r"(a[3]), "r"(b[0]), "r"(b[1]));
}

// MODE 0: fp32 out (+bias). MODE 1: bias + exact GELU, split bf16 out.
template<int MODE>
__global__ __launch_bounds__(256, 2) void gemm_bf16x3(GemmArgs P, int K, int N)
{
    extern __shared__ __align__(16) __nv_bfloat16 sm[];

    const int z = blockIdx.z;
    const __nv_bfloat16* __restrict__ Ah = P.Ah;
    const __nv_bfloat16* __restrict__ Al = P.Al;
    const __nv_bfloat16* __restrict__ Bh = P.Bh[z];
    const __nv_bfloat16* __restrict__ Bl = P.Bl[z];
    const float* __restrict__ bias = P.bias[z];

    const int n0 = blockIdx.x * BN;
    const int m0 = blockIdx.y * BM;
    const int tid  = threadIdx.x;
    const int lane = tid & 31;
    const int warp = tid >> 5;
    const int warpM = warp >> 2;   // 0..1
    const int warpN = warp & 3;    // 0..3

    const int nT = K / BK2;

    auto issue = [&](int t, int s) {
        const int k0 = t * BK2;
#pragma unroll
        for (int p = 0; p < 2; p++) {
            const int idx = tid + p * 256;
            const int ar = idx >> 2, acc_ = idx & 3;           // 128 rows x 4 chunks
            cpa16(sm + ASOFFZ(s, 0, ar, acc_), Ah + (size_t)(m0 + ar) * K + k0 + acc_ * 8);
            cpa16(sm + ASOFFZ(s, 1, ar, acc_), Al + (size_t)(m0 + ar) * K + k0 + acc_ * 8);
            const int br = idx >> 4, bcc = idx & 15;           // 32 rows x 16 chunks
            cpa16(sm + BSOFFZ(s, 0, br, bcc), Bh + (size_t)(k0 + br) * N + n0 + bcc * 8);
            cpa16(sm + BSOFFZ(s, 1, br, bcc), Bl + (size_t)(k0 + br) * N + n0 + bcc * 8);
        }
        asm volatile("cp.async.commit_group;" ::: "memory");
    };

    issue(0, 0);
    issue(1, 1);

    float acc[4][4][4] = {};
    int s = 0;

    for (int t = 0; t < nT; t++) {
        if (t + 1 < nT) asm volatile("cp.async.wait_group 1;" ::: "memory");
        else            asm volatile("cp.async.wait_group 0;" ::: "memory");
        __syncthreads();

#pragma unroll
        for (int sub = 0; sub < 2; sub++) {
            uint32_t ah[4][4], al[4][4], bh[4][2], bl[4][2];
            const int cA = sub * 2 + (lane >> 4);              // A 16B chunk
#pragma unroll
            for (int mi = 0; mi < 4; mi++) {
                const int arow = warpM * 64 + mi * 16 + (lane & 15);
                ldsm4(ah[mi], sm + ASOFFZ(s, 0, arow, cA));
                ldsm4(al[mi], sm + ASOFFZ(s, 1, arow, cA));
            }
            const int brow = sub * 16 + (lane & 15);
#pragma unroll
            for (int pr = 0; pr < 2; pr++) {
                const int cB = warpN * 4 + pr * 2 + (lane >> 4);  // B 16B chunk
                uint32_t tmp[4];
                ldsm4t(tmp, sm + BSOFFZ(s, 0, brow, cB));
                bh[pr * 2][0] = tmp[0]; bh[pr * 2][1] = tmp[1];
                bh[pr * 2 + 1][0] = tmp[2]; bh[pr * 2 + 1][1] = tmp[3];
                ldsm4t(tmp, sm + BSOFFZ(s, 1, brow, cB));
                bl[pr * 2][0] = tmp[0]; bl[pr * 2][1] = tmp[1];
                bl[pr * 2 + 1][0] = tmp[2]; bl[pr * 2 + 1][1] = tmp[3];
            }
#pragma unroll
            for (int mi = 0; mi < 4; mi++)
#pragma unroll
                for (int ni = 0; ni < 4; ni++) {
                    mma16816(acc[mi][ni], ah[mi], bh[ni]);
                    mma16816(acc[mi][ni], ah[mi], bl[ni]);
                    mma16816(acc[mi][ni], al[mi], bh[ni]);
                }
        }
        if (t + 2 < nT) {
            int s2 = s + 2; if (s2 >= 3) s2 -= 3;
            issue(t + 2, s2);
        }
        if (++s == 3) s = 0;
    }

    // epilogue
    const int g  = lane >> 2;
    const int tg = lane & 3;
#pragma unroll
    for (int mi = 0; mi < 4; mi++) {
#pragma unroll
        for (int ni = 0; ni < 4; ni++) {
            const int row = m0 + warpM * 64 + mi * 16 + g;
            const int col = n0 + warpN * 32 + ni * 8 + tg * 2;
            const float b0 = bias[col], b1 = bias[col + 1];
            float v0 = acc[mi][ni][0] + b0;
            float v1 = acc[mi][ni][1] + b1;
            float v2 = acc[mi][ni][2] + b0;
            float v3 = acc[mi][ni][3] + b1;
            if (MODE == 1) {
                v0 = 0.5f * v0 * (1.0f + erff(v0 * 0.70710678118654752f));
                v1 = 0.5f * v1 * (1.0f + erff(v1 * 0.70710678118654752f));
                v2 = 0.5f * v2 * (1.0f + erff(v2 * 0.70710678118654752f));
                v3 = 0.5f * v3 * (1.0f + erff(v3 * 0.70710678118654752f));
                uint32_t hw, lw;
                split2(v0, v1, hw, lw);
                *(uint32_t*)(P.Ch + (size_t)row * N + col) = hw;
                *(uint32_t*)(P.Cl + (size_t)row * N + col) = lw;
                split2(v2, v3, hw, lw);
                *(uint32_t*)(P.Ch + (size_t)(row + 8) * N + col) = hw;
                *(uint32_t*)(P.Cl + (size_t)(row + 8) * N + col) = lw;
            } else {
                float* C = P.C[z];
                *(float2*)(C + (size_t)row * N + col)       = make_float2(v0, v1);
                *(float2*)(C + (size_t)(row + 8) * N + col) = make_float2(v2, v3);
            }
        }
    }
}

// ---------------- fused attention (flash-style, fp32; split bf16 out) ----------------
#define SMPAD 65
__global__ __launch_bounds__(256) void attention_kernel(
    const float* __restrict__ q, const float* __restrict__ k,
    const float* __restrict__ v, const float* __restrict__ mask,
    __nv_bfloat16* __restrict__ ctx_h, __nv_bfloat16* __restrict__ ctx_l)
{
    extern __shared__ float smf[];
    float* Qs = smf;
    float* Ks = Qs + 64 * SMPAD;
    float* Vs = Ks + 64 * SMPAD;
    float* Ps = Vs + 64 * SMPAD;
    float* rm = Ps + 64 * SMPAD;
    float* rl = rm + 64;
    float* rs = rl + 64;
    float* am = rs + 64;

    const int tx = threadIdx.x, ty = threadIdx.y;
    const int tid = ty * 16 + tx;
    const int bh = blockIdx.y;
    const int b = bh / NHz, h = bh % NHz;
    const int i0 = blockIdx.x * 64;
    const float scale = 0.125f;

#pragma unroll
    for (int it = 0; it < 4; it++) {
        int idx = tid + it * 256;
        int row = idx >> 4;
        int d4 = (idx & 15) * 4;
        float4 t = *(const float4*)(q + (size_t)(b * Tz + i0 + row) * Hz + h * HDz + d4);
        Qs[row * SMPAD + d4 + 0] = t.x;
        Qs[row * SMPAD + d4 + 1] = t.y;
        Qs[row * SMPAD + d4 + 2] = t.z;
        Qs[row * SMPAD + d4 + 3] = t.w;
    }
    if (tid < 64) { rm[tid] = -1e30f; rl[tid] = 0.0f; }

    float acc[4][4] = {};

    for (int jc = 0; jc < Tz / 64; jc++) {
        const int j0 = jc * 64;
#pragma unroll
        for (int it = 0; it < 4; it++) {
            int idx = tid + it * 256;
            int row = idx >> 4;
            int d4 = (idx & 15) * 4;
            float4 t = *(const float4*)(k + (size_t)(b * Tz + j0 + row) * Hz + h * HDz + d4);
            Ks[row * SMPAD + d4 + 0] = t.x;
            Ks[row * SMPAD + d4 + 1] = t.y;
            Ks[row * SMPAD + d4 + 2] = t.z;
            Ks[row * SMPAD + d4 + 3] = t.w;
        }
        if (tid < 64) am[tid] = (1.0f - mask[b * Tz + j0 + tid]) * -10000.0f;
        __syncthreads();

        float s[4][4] = {};
#pragma unroll 4
        for (int d = 0; d < 64; d++) {
            float qv[4], kv[4];
#pragma unroll
            for (int i = 0; i < 4; i++) qv[i] = Qs[(ty + 16 * i) * SMPAD + d];
#pragma unroll
            for (int j = 0; j < 4; j++) kv[j] = Ks[(tx + 16 * j) * SMPAD + d];
#pragma unroll
            for (int i = 0; i < 4; i++)
#pragma unroll
                for (int j = 0; j < 4; j++)
                    s[i][j] = fmaf(qv[i], kv[j], s[i][j]);
        }
#pragma unroll
        for (int i = 0; i < 4; i++)
#pragma unroll
            for (int j = 0; j < 4; j++)
                Ps[(ty + 16 * i) * SMPAD + tx + 16 * j] = s[i][j] * scale + am[tx + 16 * j];
        __syncthreads();

        // load V chunk
#pragma unroll
        for (int it = 0; it < 4; it++) {
            int idx = tid + it * 256;
            int row = idx >> 4;
            int d4 = (idx & 15) * 4;
            float4 t = *(const float4*)(v + (size_t)(b * Tz + j0 + row) * Hz + h * HDz + d4);
            Vs[row * SMPAD + d4 + 0] = t.x;
            Vs[row * SMPAD + d4 + 1] = t.y;
            Vs[row * SMPAD + d4 + 2] = t.z;
            Vs[row * SMPAD + d4 + 3] = t.w;
        }

        // parallel online softmax: 4 threads per row, 16 cols each
        {
            const int srow = tid >> 2;
            const int ssub = tid & 3;
            float* prow = Ps + srow * SMPAD + ssub * 16;
            const float mo = rm[srow];
            float pv[16];
            float cm = -1e30f;
#pragma unroll
            for (int jj = 0; jj < 16; jj++) {
                pv[jj] = prow[jj];
                cm = fmaxf(cm, pv[jj]);
            }
            cm = fmaxf(cm, __shfl_xor_sync(0xffffffffu, cm, 1));
            cm = fmaxf(cm, __shfl_xor_sync(0xffffffffu, cm, 2));
            const float nm = fmaxf(mo, cm);
            float sum = 0.0f;
#pragma unroll
            for (int jj = 0; jj < 16; jj++) {
                float p = __expf(pv[jj] - nm);
                prow[jj] = p;
                sum += p;
            }
            sum += __shfl_xor_sync(0xffffffffu, sum, 1);
            sum += __shfl_xor_sync(0xffffffffu, sum, 2);
            if (ssub == 0) {
                const float sc = __expf(mo - nm);
                rl[srow] = rl[srow] * sc + sum;
                rm[srow] = nm;
                rs[srow] = sc;
            }
        }
        __syncthreads();

#pragma unroll
        for (int i = 0; i < 4; i++) {
            const float sc = rs[ty + 16 * i];
#pragma unroll
            for (int j = 0; j < 4; j++) acc[i][j] *= sc;
        }
#pragma unroll 4
        for (int jj = 0; jj < 64; jj++) {
            float pv[4], vv[4];
#pragma unroll
            for (int i = 0; i < 4; i++) pv[i] = Ps[(ty + 16 * i) * SMPAD + jj];
#pragma unroll
            for (int j = 0; j < 4; j++) vv[j] = Vs[jj * SMPAD + tx + 16 * j];
#pragma unroll
            for (int i = 0; i < 4; i++)
#pragma unroll
                for (int j = 0; j < 4; j++)
                    acc[i][j] = fmaf(pv[i], vv[j], acc[i][j]);
        }
        __syncthreads();
    }

#pragma unroll
    for (int i = 0; i < 4; i++) {
        const float inv = 1.0f / rl[ty + 16 * i];
#pragma unroll
        for (int j = 0; j < 4; j++) {
            size_t off = (size_t)(b * Tz + i0 + ty + 16 * i) * Hz + h * HDz + tx + 16 * j;
            float val = acc[i][j] * inv;
            __nv_bfloat16 hv, lv;
            split1(val, hv, lv);
            ctx_h[off] = hv;
            ctx_l[off] = lv;
        }
    }
}

// ---------------- residual + LayerNorm (fp32 + split out) ----------------
__device__ __forceinline__ float block_reduce_sum(float val, float* red) {
    const int lane = threadIdx.x & 31, w = threadIdx.x >> 5;
#pragma unroll
    for (int o = 16; o > 0; o >>= 1) val += __shfl_down_sync(0xffffffffu, val, o);
    if (lane == 0) red[w] = val;
    __syncthreads();
    if (w == 0) {
        float t = (lane < 8) ? red[lane] : 0.0f;
#pragma unroll
        for (int o = 4; o > 0; o >>= 1) t += __shfl_down_sync(0xffffffffu, t, o);
        if (lane == 0) red[0] = t;
    }
    __syncthreads();
    float r = red[0];
    __syncthreads();
    return r;
}

__global__ __launch_bounds__(256) void ln_kernel(
    const float* __restrict__ a, const float* __restrict__ res,
    const float* __restrict__ g, const float* __restrict__ bb,
    float* __restrict__ out,
    __nv_bfloat16* __restrict__ oh, __nv_bfloat16* __restrict__ ol)
{
    __shared__ float buf[Hz];
    __shared__ float red[32];
    const int row = blockIdx.x;
    const float* ap = a + (size_t)row * Hz;
    const float* rp = res + (size_t)row * Hz;

    float ls = 0.0f;
    for (int i = threadIdx.x; i < Hz; i += 256) {
        float vv = ap[i] + rp[i];
        buf[i] = vv;
        ls += vv;
    }
    const float mean = block_reduce_sum(ls, red) * (1.0f / Hz);

    float lq = 0.0f;
    for (int i = threadIdx.x; i < Hz; i += 256) {
        float d = buf[i] - mean;
        lq += d * d;
    }
    const float var = block_reduce_sum(lq, red) * (1.0f / Hz);
    const float rstd = rsqrtf(var + 1e-12f);

    for (int i = threadIdx.x; i < Hz; i += 256) {
        float y = (buf[i] - mean) * rstd * g[i] + bb[i];
        out[(size_t)row * Hz + i] = y;
        __nv_bfloat16 hv, lv;
        split1(y, hv, lv);
        oh[(size_t)row * Hz + i] = hv;
        ol[(size_t)row * Hz + i] = lv;
    }
}

// ---------------- launch ----------------
extern "C" void kernel_launch(void* const* d_in, const int* in_sizes, int n_in,
                              void* d_out, int out_size)
{
    const float* hidden = (const float*)d_in[0];
    const float* mask   = (const float*)d_in[1];
    const float* Wq  = (const float*)d_in[2];   const float* bq  = (const float*)d_in[3];
    const float* Wk  = (const float*)d_in[4];   const float* bk  = (const float*)d_in[5];
    const float* Wv  = (const float*)d_in[6];   const float* bv  = (const float*)d_in[7];
    const float* Wao = (const float*)d_in[8];   const float* bao = (const float*)d_in[9];
    const float* g1  = (const float*)d_in[10];  const float* b1  = (const float*)d_in[11];
    const float* Wi  = (const float*)d_in[12];  const float* bi  = (const float*)d_in[13];
    const float* Wo  = (const float*)d_in[14];  const float* bo  = (const float*)d_in[15];
    const float* g2  = (const float*)d_in[16];  const float* b2  = (const float*)d_in[17];
    float* out = (float*)d_out;

    float *q, *k, *v, *proj, *attn, *xb;
    cudaGetSymbolAddress((void**)&q,    g_q);
    cudaGetSymbolAddress((void**)&k,    g_k);
    cudaGetSymbolAddress((void**)&v,    g_v);
    cudaGetSymbolAddress((void**)&proj, g_proj);
    cudaGetSymbolAddress((void**)&attn, g_attn);
    cudaGetSymbolAddress((void**)&xb,   g_x);

    __nv_bfloat16 *xh, *xl, *ath, *atl, *cth, *ctl, *ffh, *ffl;
    cudaGetSymbolAddress((void**)&xh,  g_x_h);    cudaGetSymbolAddress((void**)&xl,  g_x_l);
    cudaGetSymbolAddress((void**)&ath, g_attn_h); cudaGetSymbolAddress((void**)&atl, g_attn_l);
    cudaGetSymbolAddress((void**)&cth, g_ctx_h);  cudaGetSymbolAddress((void**)&ctl, g_ctx_l);
    cudaGetSymbolAddress((void**)&ffh, g_ff_h);   cudaGetSymbolAddress((void**)&ffl, g_ff_l);

    __nv_bfloat16 *wqh, *wql, *wkh, *wkl, *wvh, *wvl, *waoh, *waol, *wih, *wil, *woh, *wol;
    cudaGetSymbolAddress((void**)&wqh,  g_wq_h);  cudaGetSymbolAddress((void**)&wql,  g_wq_l);
    cudaGetSymbolAddress((void**)&wkh,  g_wk_h);  cudaGetSymbolAddress((void**)&wkl,  g_wk_l);
    cudaGetSymbolAddress((void**)&wvh,  g_wv_h);  cudaGetSymbolAddress((void**)&wvl,  g_wv_l);
    cudaGetSymbolAddress((void**)&waoh, g_wao_h); cudaGetSymbolAddress((void**)&waol, g_wao_l);
    cudaGetSymbolAddress((void**)&wih,  g_wi_h);  cudaGetSymbolAddress((void**)&wil,  g_wi_l);
    cudaGetSymbolAddress((void**)&woh,  g_wo_h);  cudaGetSymbolAddress((void**)&wol,  g_wo_l);

    // pre-split weights + input
    const int nHH = Lz * Hz * Hz, nHF = Lz * Hz * FFz, nX = Mz * Hz;
    split_kernel<<<nHH / 1024, 256>>>(Wq,  wqh,  wql,  nHH / 4);
    split_kernel<<<nHH / 1024, 256>>>(Wk,  wkh,  wkl,  nHH / 4);
    split_kernel<<<nHH / 1024, 256>>>(Wv,  wvh,  wvl,  nHH / 4);
    split_kernel<<<nHH / 1024, 256>>>(Wao, waoh, waol, nHH / 4);
    split_kernel<<<nHF / 1024, 256>>>(Wi,  wih,  wil,  nHF / 4);
    split_kernel<<<nHF / 1024, 256>>>(Wo,  woh,  wol,  nHF / 4);
    split_kernel<<<nX  / 1024, 256>>>(hidden, xh, xl, nX / 4);

    const size_t att_smem  = (size_t)(4 * 64 * SMPAD + 4 * 64) * sizeof(float);
    cudaFuncSetAttribute(attention_kernel,
                         cudaFuncAttributeMaxDynamicSharedMemorySize, (int)att_smem);
    cudaFuncSetAttribute(gemm_bf16x3<0>,
                         cudaFuncAttributeMaxDynamicSharedMemorySize, GEMM_SMEM);
    cudaFuncSetAttribute(gemm_bf16x3<1>,
                         cudaFuncAttributeMaxDynamicSharedMemorySize, GEMM_SMEM);

    dim3 gAtt(Tz / 64, Bz * NHz);
    dim3 blkA(16, 16);

    for (int l = 0; l < Lz; l++) {
        const float* xres = (l == 0) ? hidden : xb;
        const size_t oHH = (size_t)l * Hz * Hz;
        const size_t oHF = (size_t)l * Hz * FFz;
        const size_t oH  = (size_t)l * Hz;
        const size_t oF  = (size_t)l * FFz;

        {   // fused QKV
            GemmArgs P = {};
            P.Ah = xh; P.Al = xl;
            P.Bh[0] = wqh + oHH; P.Bl[0] = wql + oHH;
            P.Bh[1] = wkh + oHH; P.Bl[1] = wkl + oHH;
            P.Bh[2] = wvh + oHH; P.Bl[2] = wvl + oHH;
            P.bias[0] = bq + oH; P.bias[1] = bk + oH; P.bias[2] = bv + oH;
            P.C[0] = q; P.C[1] = k; P.C[2] = v;
            gemm_bf16x3<0><<<dim3(Hz / BN, Mz / BM, 3), 256, GEMM_SMEM>>>(P, Hz, Hz);
        }

        attention_kernel<<<gAtt, blkA, att_smem>>>(q, k, v, mask, cth, ctl);

        {   // attention output projection
            GemmArgs P = {};
            P.Ah = cth; P.Al = ctl;
            P.Bh[0] = waoh + oHH; P.Bl[0] = waol + oHH;
            P.bias[0] = bao + oH;
            P.C[0] = proj;
            gemm_bf16x3<0><<<dim3(Hz / BN, Mz / BM, 1), 256, GEMM_SMEM>>>(P, Hz, Hz);
        }
        ln_kernel<<<Mz, 256>>>(proj, xres, g1 + oH, b1 + oH, attn, ath, atl);

        {   // FF1 + GELU (split bf16 out)
            GemmArgs P = {};
            P.Ah = ath; P.Al = atl;
            P.Bh[0] = wih + oHF; P.Bl[0] = wil + oHF;
            P.bias[0] = bi + oF;
            P.Ch = ffh; P.Cl = ffl;
            gemm_bf16x3<1><<<dim3(FFz / BN, Mz / BM, 1), 256, GEMM_SMEM>>>(P, Hz, FFz);
        }
        {   // FF2
            GemmArgs P = {};
            P.Ah = ffh; P.Al = ffl;
            P.Bh[0] = woh + oHF; P.Bl[0] = wol + oHF;
            P.bias[0] = bo + oH;
            P.C[0] = proj;
            gemm_bf16x3<0><<<dim3(Hz / BN, Mz / BM, 1), 256, GEMM_SMEM>>>(P, FFz, Hz);
        }
        ln_kernel<<<Mz, 256>>>(proj, attn, g2 + oH, b2 + oH,
                               (l == Lz - 1) ? out : xb, xh, xl);
    }
}